// round 8
// baseline (speedup 1.0000x reference)
#include <cuda_runtime.h>
#include <math.h>

#define PNT 20
#define KNN 8
#define D0  128
#define MAXN 8192
typedef unsigned long long ull;

__device__ float g_xw [ (size_t)MAXN*PNT*512 ];
__device__ float g_act[ (size_t)MAXN*PNT*512 ];
__device__ float g_nm [ (size_t)MAXN*PNT*PNT ];

__device__ __forceinline__ ull pack2f(float x, float y){
    return ((ull)__float_as_uint(y) << 32) | (ull)__float_as_uint(x);
}
__device__ __forceinline__ ull ffma2(ull a, ull b, ull c){
    ull d;
    asm("fma.rn.f32x2 %0, %1, %2, %3;" : "=l"(d) : "l"(a), "l"(b), "l"(c));
    return d;
}
__device__ __forceinline__ float lo2(ull v){ return __uint_as_float((unsigned)(v & 0xffffffffull)); }
__device__ __forceinline__ float hi2(ull v){ return __uint_as_float((unsigned)(v >> 32)); }
__device__ __forceinline__ float warp_sum(float v){
    #pragma unroll
    for(int m=16;m>0;m>>=1) v += __shfl_xor_sync(0xffffffffu, v, m);
    return v;
}

// ============================================================================
// sgemm: C[M,N] = A[M,K] @ B[K,N], row-major, all dims multiples of 128/128/16
// 128x128 block tile, BK=16, double buffered, 8x8 thread tile via ffma2.
// ============================================================================
__global__ void __launch_bounds__(256,2)
sgemm_kernel(const float* __restrict__ A, const float* __restrict__ B,
             float* __restrict__ C, int M, int N, int K)
{
    __shared__ float As[2][16][128];   // transposed: As[k][m]
    __shared__ float Bs[2][16][128];   // Bs[k][n]
    const int tid = threadIdx.x;
    const int m0 = blockIdx.y * 128, n0 = blockIdx.x * 128;
    const int tx = tid & 15, ty = tid >> 4;
    const int ar = tid >> 2, ac = (tid & 3) * 4;   // A: rows ar, ar+64; cols ac..ac+3
    const int br = tid >> 5, bc = (tid & 31) * 4;  // B: rows br, br+8

    const float* Ag = A + (long long)(m0 + ar) * K + ac;
    const float* Bg = B + (long long)br * N + (n0 + bc);

    // prologue: tile 0
    float4 a0 = *(const float4*)(Ag);
    float4 a1 = *(const float4*)(Ag + (long long)64 * K);
    float4 b0 = *(const float4*)(Bg);
    float4 b1 = *(const float4*)(Bg + (long long)8 * N);
    As[0][ac+0][ar] = a0.x; As[0][ac+1][ar] = a0.y;
    As[0][ac+2][ar] = a0.z; As[0][ac+3][ar] = a0.w;
    As[0][ac+0][ar+64] = a1.x; As[0][ac+1][ar+64] = a1.y;
    As[0][ac+2][ar+64] = a1.z; As[0][ac+3][ar+64] = a1.w;
    *(float4*)&Bs[0][br  ][bc] = b0;
    *(float4*)&Bs[0][br+8][bc] = b1;
    __syncthreads();

    ull acc[4][8];
    #pragma unroll
    for(int r=0;r<4;r++){
        #pragma unroll
        for(int c=0;c<8;c++) acc[r][c]=0ull;
    }

    const int nk = K >> 4;
    for(int t=0;t<nk;t++){
        const int cur = t & 1;
        float4 na0,na1,nb0,nb1;
        if(t+1<nk){
            const float* Ag2 = Ag + (t+1)*16;
            const float* Bg2 = Bg + (long long)((t+1)*16) * N;
            na0 = *(const float4*)(Ag2);
            na1 = *(const float4*)(Ag2 + (long long)64 * K);
            nb0 = *(const float4*)(Bg2);
            nb1 = *(const float4*)(Bg2 + (long long)8 * N);
        }
        #pragma unroll
        for(int k=0;k<16;k++){
            ulonglong2 p0 = *(const ulonglong2*)&As[cur][k][ty*8];
            ulonglong2 p1 = *(const ulonglong2*)&As[cur][k][ty*8+4];
            float4 q0 = *(const float4*)&Bs[cur][k][tx*8];
            float4 q1 = *(const float4*)&Bs[cur][k][tx*8+4];
            ull a2[4] = {p0.x, p0.y, p1.x, p1.y};
            float bb[8] = {q0.x,q0.y,q0.z,q0.w, q1.x,q1.y,q1.z,q1.w};
            #pragma unroll
            for(int c=0;c<8;c++){
                ull w = pack2f(bb[c], bb[c]);
                #pragma unroll
                for(int r=0;r<4;r++) acc[r][c] = ffma2(a2[r], w, acc[r][c]);
            }
        }
        if(t+1<nk){
            const int nxt = cur ^ 1;
            As[nxt][ac+0][ar] = na0.x; As[nxt][ac+1][ar] = na0.y;
            As[nxt][ac+2][ar] = na0.z; As[nxt][ac+3][ar] = na0.w;
            As[nxt][ac+0][ar+64] = na1.x; As[nxt][ac+1][ar+64] = na1.y;
            As[nxt][ac+2][ar+64] = na1.z; As[nxt][ac+3][ar+64] = na1.w;
            *(float4*)&Bs[nxt][br  ][bc] = nb0;
            *(float4*)&Bs[nxt][br+8][bc] = nb1;
        }
        __syncthreads();
    }

    // write 8x8 result
    #pragma unroll
    for(int r=0;r<4;r++){
        float4 vlo0 = make_float4(lo2(acc[r][0]), lo2(acc[r][1]), lo2(acc[r][2]), lo2(acc[r][3]));
        float4 vlo1 = make_float4(lo2(acc[r][4]), lo2(acc[r][5]), lo2(acc[r][6]), lo2(acc[r][7]));
        float4 vhi0 = make_float4(hi2(acc[r][0]), hi2(acc[r][1]), hi2(acc[r][2]), hi2(acc[r][3]));
        float4 vhi1 = make_float4(hi2(acc[r][4]), hi2(acc[r][5]), hi2(acc[r][6]), hi2(acc[r][7]));
        float* c0 = C + (long long)(m0 + ty*8 + 2*r    ) * N + n0 + tx*8;
        float* c1 = C + (long long)(m0 + ty*8 + 2*r + 1) * N + n0 + tx*8;
        *(float4*)(c0)   = vlo0; *(float4*)(c0+4) = vlo1;
        *(float4*)(c1)   = vhi0; *(float4*)(c1+4) = vhi1;
    }
}

// ============================================================================
// graph: per-sample Gram -> d2 -> kNN -> normalized adjacency NmT[s][t] -> gmem
// ============================================================================
template<int IN>
__global__ void __launch_bounds__(256)
graph_kernel(const float* __restrict__ act, float* __restrict__ nm)
{
    __shared__ float Ap[PNT*IN];          // points-major: Ap[p*IN + f]
    __shared__ float G[PNT*PNT];
    __shared__ float d2[PNT*PNT];
    __shared__ float NmT[PNT*PNT];
    __shared__ int   knn[PNT*KNN];
    __shared__ int   deg[PNT];
    __shared__ float dinv[PNT];

    const int tid = threadIdx.x, warp = tid >> 5, lane = tid & 31;
    const long long b = blockIdx.x;
    const float* src = act + b * (long long)(PNT*IN);
    for(int q=tid;q<PNT*IN;q+=256) Ap[q]=src[q];
    __syncthreads();

    // Gram incl diagonal: 210 (i<=j) pairs; 4 in flight per warp so the
    // shfl reduction chains pipeline.
    for(int q0 = warp*4; q0 < 210; q0 += 32){
        int ii[4], jj[4]; float accv[4];
        #pragma unroll
        for(int u=0;u<4;u++){
            int q = q0+u; if(q >= 210) q = 0;
            int i=0, rem=q;
            while(rem >= PNT-i){ rem -= PNT-i; i++; }
            ii[u]=i; jj[u]=i+rem;
        }
        #pragma unroll
        for(int u=0;u<4;u++){
            const float4* ri = (const float4*)&Ap[ii[u]*IN];
            const float4* rj = (const float4*)&Ap[jj[u]*IN];
            float s = 0.f;
            #pragma unroll
            for(int c=0;c<IN/128;c++){
                float4 av = ri[lane + c*32], bv = rj[lane + c*32];
                s = fmaf(av.x,bv.x,s); s = fmaf(av.y,bv.y,s);
                s = fmaf(av.z,bv.z,s); s = fmaf(av.w,bv.w,s);
            }
            accv[u]=s;
        }
        #pragma unroll
        for(int u=0;u<4;u++) accv[u]=warp_sum(accv[u]);
        if(lane==0){
            #pragma unroll
            for(int u=0;u<4;u++) if(q0+u<210){
                G[ii[u]*PNT+jj[u]] = accv[u];
                G[jj[u]*PNT+ii[u]] = accv[u];
            }
        }
    }
    __syncthreads();
    // d2[i][j] = sq_i + sq_j - 2*dot (exact reference formula); self = -inf
    // NOTE: strided — PNT*PNT=400 > blockDim
    for(int q=tid;q<PNT*PNT;q+=256){
        int i = q/PNT, j = q%PNT;
        d2[q] = (i==j) ? __int_as_float(0xff800000)
                       : G[i*PNT+i] + G[j*PNT+j] - 2.f*G[i*PNT+j];
    }
    __syncthreads();
    // stable K-smallest selection (matches stable argsort tie-breaking);
    // -inf self is picked first and dropped.
    if(tid<PNT){
        float row[PNT];
        #pragma unroll
        for(int j=0;j<PNT;j++) row[j]=d2[tid*PNT+j];
        unsigned used=0;
        #pragma unroll
        for(int k=0;k<KNN+1;k++){
            float best = __int_as_float(0x7f800000); int bj=0;
            #pragma unroll
            for(int j=0;j<PNT;j++){
                if( !((used>>j)&1u) && row[j] < best ){ best=row[j]; bj=j; }
            }
            used |= 1u<<bj;
            if(k>0) knn[tid*KNN + (k-1)] = bj;
        }
        deg[tid]=1;    // self loop
    }
    for(int q=tid;q<PNT*PNT;q+=256) NmT[q]=0.f;
    __syncthreads();
    if(tid<PNT*KNN) atomicAdd(&deg[knn[tid]], 1);
    __syncthreads();
    if(tid<PNT) dinv[tid] = 1.f/sqrtf((float)deg[tid]);
    __syncthreads();
    if(tid<PNT*KNN){
        int u = tid>>3;            // source
        int t = knn[tid];          // target
        NmT[u*PNT+t] = dinv[t]*dinv[u];
    }
    if(tid<PNT) NmT[tid*PNT+tid] = dinv[tid]*dinv[tid];
    __syncthreads();
    // NOTE: strided — 400 > 256
    for(int q=tid;q<PNT*PNT;q+=256) nm[b*(PNT*PNT) + q] = NmT[q];
}

// ============================================================================
// aggregate: act[b][t][o] = relu( sum_s NmT[s][t]*xw[b][s][o] + bias[o] )
// ============================================================================
template<int OUT>
__global__ void __launch_bounds__(256)
aggregate_kernel(const float* __restrict__ xw, const float* __restrict__ nm,
                 const float* __restrict__ bias, float* __restrict__ act)
{
    __shared__ __align__(16) float NmT[PNT*PNT];
    const int tid = threadIdx.x;
    const long long b = blockIdx.x;
    for(int q=tid;q<PNT*PNT;q+=256) NmT[q]=nm[b*(PNT*PNT)+q];
    __syncthreads();

    const float* xwb  = xw  + b*(long long)(PNT*OUT);
    float*       actb = act + b*(long long)(PNT*OUT);
    constexpr int NO = (OUT + 255)/256;
    const ull* nm2 = (const ull*)NmT;

    ull acc[NO][PNT/2];
    #pragma unroll
    for(int j=0;j<NO;j++){
        #pragma unroll
        for(int th=0;th<PNT/2;th++) acc[j][th]=0ull;
    }
    #pragma unroll 2
    for(int s=0;s<PNT;s++){
        const ull* nrow = nm2 + s*(PNT/2);
        #pragma unroll
        for(int j=0;j<NO;j++){
            int o = tid + j*256;
            float v = (o < OUT) ? xwb[s*OUT + o] : 0.f;
            ull vv = pack2f(v,v);
            #pragma unroll
            for(int th=0;th<PNT/2;th++) acc[j][th]=ffma2(nrow[th], vv, acc[j][th]);
        }
    }
    #pragma unroll
    for(int j=0;j<NO;j++){
        int o = tid + j*256;
        if(o < OUT){
            float bo = bias[o];
            #pragma unroll
            for(int th=0;th<PNT/2;th++){
                actb[(2*th  )*OUT + o] = fmaxf(lo2(acc[j][th]) + bo, 0.f);
                actb[(2*th+1)*OUT + o] = fmaxf(hi2(acc[j][th]) + bo, 0.f);
            }
        }
    }
}

// ============================================================================
// head: mean pool (over 20 pts, 128 feat) -> fc 128x64 relu -> fc 64x3 -> softmax
// ============================================================================
__global__ void __launch_bounds__(128)
head_kernel(const float* __restrict__ act,
            const float* __restrict__ W4, const float* __restrict__ b4,
            const float* __restrict__ W5, const float* __restrict__ b5,
            float* __restrict__ out)
{
    __shared__ float msm[128], hsm[64], lsm[3];
    const int tid = threadIdx.x;
    const long long b = blockIdx.x;
    const float* ab = act + b*(long long)(PNT*128);
    {
        float s=0.f;
        #pragma unroll
        for(int p=0;p<PNT;p++) s += ab[p*128 + tid];
        msm[tid] = s * (1.f/PNT);
    }
    __syncthreads();
    if(tid<64){
        float a=b4[tid];
        #pragma unroll 4
        for(int f=0;f<128;f++) a = fmaf(msm[f], W4[f*64+tid], a);
        hsm[tid]=fmaxf(a,0.f);
    }
    __syncthreads();
    if(tid<3){
        float a=b5[tid];
        #pragma unroll
        for(int j=0;j<64;j++) a = fmaf(hsm[j], W5[j*3+tid], a);
        lsm[tid]=a;
    }
    __syncthreads();
    if(tid==0){
        float l0=lsm[0], l1=lsm[1], l2=lsm[2];
        float m=fmaxf(l0,fmaxf(l1,l2));
        float e0=expf(l0-m), e1=expf(l1-m), e2=expf(l2-m);
        float s=e0+e1+e2;
        out[b*3+0]=e0/s; out[b*3+1]=e1/s; out[b*3+2]=e2/s;
    }
}

extern "C" void kernel_launch(void* const* d_in, const int* in_sizes, int n_in,
                              void* d_out, int out_size){
    const float* x  = (const float*)d_in[0];
    const float* W1 = (const float*)d_in[1];
    const float* b1 = (const float*)d_in[2];
    const float* W2 = (const float*)d_in[3];
    const float* b2 = (const float*)d_in[4];
    const float* W3 = (const float*)d_in[5];
    const float* b3 = (const float*)d_in[6];
    const float* W4 = (const float*)d_in[7];
    const float* b4 = (const float*)d_in[8];
    const float* W5 = (const float*)d_in[9];
    const float* b5 = (const float*)d_in[10];
    float* out = (float*)d_out;

    const int NS = in_sizes[0]/(PNT*D0);   // 8192
    const int M  = NS*PNT;                 // 163840 (multiple of 128)

    float *xw, *act, *nm;
    cudaGetSymbolAddress((void**)&xw,  g_xw);
    cudaGetSymbolAddress((void**)&act, g_act);
    cudaGetSymbolAddress((void**)&nm,  g_nm);

    // layer 1: 128 -> 256
    graph_kernel<128><<<NS,256>>>(x, nm);
    sgemm_kernel<<<dim3(256/128, M/128),256>>>(x,  W1, xw, M, 256, 128);
    aggregate_kernel<256><<<NS,256>>>(xw, nm, b1, act);
    // layer 2: 256 -> 512
    graph_kernel<256><<<NS,256>>>(act, nm);
    sgemm_kernel<<<dim3(512/128, M/128),256>>>(act, W2, xw, M, 512, 256);
    aggregate_kernel<512><<<NS,256>>>(xw, nm, b2, act);
    // layer 3: 512 -> 128
    graph_kernel<512><<<NS,256>>>(act, nm);
    sgemm_kernel<<<dim3(128/128, M/128),256>>>(act, W3, xw, M, 128, 512);
    aggregate_kernel<128><<<NS,256>>>(xw, nm, b3, act);
    // head
    head_kernel<<<NS,128>>>(act, W4, b4, W5, b5, out);
}